// round 11
// baseline (speedup 1.0000x reference)
#include <cuda_runtime.h>
#include <cuda_fp16.h>
#include <cstdint>

#define IN_DIM   64
#define HID      128
#define HID2     256
#define OUT_DIM  64
#define NSTEPS   20
#define NTHREADS 512
#define NWARP    16
#define M_TILE   64
#define KCH      32            // K rows per staged chunk (2 k16 blocks = 1 pair)
#define NSLOT    2
#define SLOTU    4096          // u32 per weight slot (chunk: 16*N = 4096 @ N=256)
#define AF_TILE_U 2048         // u32 per m16 tile in Af (16 kb * 128)
#define HS       132           // Acc row stride (floats), conflict-light

static constexpr float DTC = 1.0f / 20.0f;

// Weights pre-packed (fp16) in b-fragment order:
// [k16pair pk][n8 j][lane(4g+t)][r], r0/r1 = b0/b1 of k16 block 2pk,
// r2/r3 = b0/b1 of block 2pk+1.  b0 = {W[16kb+2t][8j+g], W[16kb+2t+1][..]},
// b1 = same with +8 on k.  uint4 arrays => 16B alignment for cp.async.bulk.
__device__ uint4 g_Wenc4[IN_DIM * HID / 8];
__device__ uint4 g_W14[HID * HID2 / 8];
__device__ uint4 g_W24[HID2 * HID2 / 8];
__device__ uint4 g_W34[HID2 * HID / 8];
__device__ uint4 g_Wdec4[HID * OUT_DIM / 8];

__device__ __forceinline__ uint32_t h2u(__half2 h) {
    return *reinterpret_cast<uint32_t*>(&h);
}

// tanh(x) = 1 - 2/(e^{2x}+1); MUFU ex2/rcp (~1e-6 err), saturates correctly.
__device__ __forceinline__ float fast_tanh(float x) {
    float e;
    asm("ex2.approx.f32 %0, %1;" : "=f"(e) : "f"(x * 2.88539008177792681472f));
    float r;
    asm("rcp.approx.f32 %0, %1;" : "=f"(r) : "f"(e + 1.0f));
    return fmaf(-2.0f, r, 1.0f);
}

__device__ __forceinline__ void mma16(float c[4], const uint4& a, uint32_t b0,
                                      uint32_t b1) {
    asm("mma.sync.aligned.m16n8k16.row.col.f32.f16.f16.f32 "
        "{%0,%1,%2,%3},{%4,%5,%6,%7},{%8,%9},{%0,%1,%2,%3};"
        : "+f"(c[0]), "+f"(c[1]), "+f"(c[2]), "+f"(c[3])
        : "r"(a.x), "r"(a.y), "r"(a.z), "r"(a.w), "r"(b0), "r"(b1));
}

// ---- mbarrier helpers ----
__device__ __forceinline__ void mbar_init(uint32_t mbar, uint32_t cnt) {
    asm volatile("mbarrier.init.shared.b64 [%0], %1;" ::"r"(mbar), "r"(cnt)
                 : "memory");
}
__device__ __forceinline__ void mbar_arrive(uint32_t mbar) {
    asm volatile("mbarrier.arrive.shared.b64 _, [%0];" ::"r"(mbar) : "memory");
}
__device__ __forceinline__ void mbar_wait(uint32_t mbar, uint32_t parity) {
    asm volatile(
        "{\n\t.reg .pred P;\n\t"
        "W_%=:\n\t"
        "mbarrier.try_wait.parity.acquire.cta.shared::cta.b64 P, [%0], %1;\n\t"
        "@!P bra W_%=;\n\t}" ::"r"(mbar),
        "r"(parity)
        : "memory");
}
__device__ __forceinline__ void stage_bulk(uint32_t dst, const void* src,
                                           uint32_t bytes, uint32_t mbar) {
    asm volatile("mbarrier.arrive.expect_tx.shared.b64 _, [%0], %1;" ::"r"(mbar),
                 "r"(bytes)
                 : "memory");
    asm volatile(
        "cp.async.bulk.shared::cta.global.mbarrier::complete_tx::bytes "
        "[%0], [%1], %2, [%3];" ::"r"(dst),
        "l"(src), "r"(bytes), "r"(mbar)
        : "memory");
}

// C[2][NF][4] += A(64 x K, fp16 fragment SMEM) * W(K x N, fp16 fragment).
// Warp grid 2(M) x 8(N); NF = N/64. Producer = tid0 stages chunks via bulk
// async into a 2-slot ring; consumers wait per-thread on full(F) mbarriers,
// arrive on empty(E) mbarriers (1/warp) when done with a slot. Block
// barriers only bracket the GEMM (Af write->read ordering).
template <int K, int N>
__device__ __forceinline__ void gemm_core(
    const uint4* __restrict__ Wg, const uint4* __restrict__ Af4,
    const uint4* __restrict__ Wb4, uint32_t wb_b, float C[2][4][4], int tile0,
    int nwp, int lane, uint32_t mbF, uint32_t mbE, uint32_t& fph,
    uint32_t& eph, int& slot, bool t0) {
    constexpr int NF = N / 64;
    constexpr int NCH = K / KCH;
    constexpr uint32_t CHU4 = 4 * N;       // uint4 per chunk (16*N u32)
    constexpr uint32_t CHB = CHU4 * 16;    // bytes per chunk
#pragma unroll
    for (int mi = 0; mi < 2; mi++)
#pragma unroll
        for (int j = 0; j < NF; j++)
#pragma unroll
            for (int e = 0; e < 4; e++) C[mi][j][e] = 0.0f;

    __syncthreads();  // prior epilogue Af writes visible before any A reads
    if (t0) {
        const int d = NCH < NSLOT ? NCH : NSLOT;
#pragma unroll
        for (int i = 0; i < d; i++) {
            int s = slot + i;
            if (s >= NSLOT) s -= NSLOT;
            mbar_wait(mbE + s * 8, (eph >> s) & 1u);
            eph ^= 1u << s;
            stage_bulk(wb_b + s * (SLOTU * 4), Wg + i * CHU4, CHB, mbF + s * 8);
        }
    }
    const uint4* Ap0 = Af4 + tile0 * (AF_TILE_U / 4) + lane;
#pragma unroll 1
    for (int ch = 0; ch < NCH; ch++) {
        const int s = slot;
        slot = (slot == NSLOT - 1) ? 0 : slot + 1;
        mbar_wait(mbF + s * 8, (fph >> s) & 1u);
        fph ^= 1u << s;
        const uint4* Ws = Wb4 + s * (SLOTU / 4);
        const int kb0 = ch * 2;
        uint4 A00 = Ap0[kb0 * 32];
        uint4 A01 = Ap0[(kb0 + 1) * 32];
        uint4 A10 = Ap0[512 + kb0 * 32];
        uint4 A11 = Ap0[512 + (kb0 + 1) * 32];
        uint4 Bv[NF];
#pragma unroll
        for (int j = 0; j < NF; j++) Bv[j] = Ws[(nwp * NF + j) * 32 + lane];
#pragma unroll
        for (int j = 0; j < NF; j++) {
            mma16(C[0][j], A00, Bv[j].x, Bv[j].y);
            mma16(C[1][j], A10, Bv[j].x, Bv[j].y);
        }
#pragma unroll
        for (int j = 0; j < NF; j++) {
            mma16(C[0][j], A01, Bv[j].z, Bv[j].w);
            mma16(C[1][j], A11, Bv[j].z, Bv[j].w);
        }
        __syncwarp();
        if ((threadIdx.x & 31) == 0) mbar_arrive(mbE + s * 8);
        if (t0 && ch + NSLOT < NCH) {
            mbar_wait(mbE + s * 8, (eph >> s) & 1u);
            eph ^= 1u << s;
            stage_bulk(wb_b + s * (SLOTU * 4), Wg + (ch + NSLOT) * CHU4, CHB,
                       mbF + s * 8);
        }
    }
    __syncthreads();  // all A reads done before epilogue rewrites Af
}

// Pack W (K x N row-major f32) into fp16 b-fragment order (u32 index i).
__device__ __forceinline__ void packW(int i, int N, const float* src,
                                      uint32_t* dst) {
    int N8 = N / 8;
    int perPk = N8 * 128;
    int pk = i / perPk;
    int rem = i - pk * perPk;
    int j = rem >> 7;
    int l = rem & 127;
    int lane = l >> 2, r = l & 3;
    int g = lane >> 2, t = lane & 3;
    int kb = 2 * pk + (r >> 1);
    int k0 = 16 * kb + 2 * t + 8 * (r & 1);
    int n = 8 * j + g;
    dst[i] = h2u(__floats2half2_rn(src[k0 * N + n], src[(k0 + 1) * N + n]));
}

__global__ void prep_kernel(const float* We, const float* W1, const float* W2,
                            const float* W3, const float* Wd) {
    int i = blockIdx.x * blockDim.x + threadIdx.x;
    if (i < IN_DIM * HID / 2) packW(i, HID, We, (uint32_t*)g_Wenc4);
    if (i < HID * HID2 / 2) packW(i, HID2, W1, (uint32_t*)g_W14);
    if (i < HID2 * HID2 / 2) packW(i, HID2, W2, (uint32_t*)g_W24);
    if (i < HID2 * HID / 2) packW(i, HID, W3, (uint32_t*)g_W34);
    if (i < HID * OUT_DIM / 2) packW(i, OUT_DIM, Wd, (uint32_t*)g_Wdec4);
}

__global__ void __launch_bounds__(NTHREADS, 2)
node_kernel(const float* __restrict__ x, const float* __restrict__ benc,
            const float* __restrict__ b1, const float* __restrict__ b2,
            const float* __restrict__ b3, const float* __restrict__ bdec,
            float* __restrict__ out) {
    extern __shared__ uint32_t smemu[];
    uint32_t* AfU = smemu;                          // [4][16][32][4] u32 (32 KB)
    uint32_t* WbU = AfU + 4 * AF_TILE_U;            // [2][SLOTU] (32 KB)
    float* Acc = (float*)(WbU + NSLOT * SLOTU);     // [64][HS] RK4 acc (33 KB)
    float* Bs = Acc + M_TILE * HS;                  // 832 f32 biases
    uint32_t* Mb = (uint32_t*)(Bs + 832);           // 4 mbarriers (32 B)

    const int tid = threadIdx.x;
    const uint32_t mbF = (uint32_t)__cvta_generic_to_shared(Mb);
    const uint32_t mbE = mbF + NSLOT * 8;
    const uint32_t wb_b = (uint32_t)__cvta_generic_to_shared(WbU);
    const bool t0 = (tid == 0);
    if (t0) {
#pragma unroll
        for (int s = 0; s < NSLOT; s++) {
            mbar_init(mbF + s * 8, 1);
            mbar_init(mbE + s * 8, NWARP);
        }
    }
    if (tid < 256) {
        Bs[tid] = b1[tid];
        Bs[256 + tid] = b2[tid];
    }
    if (tid < 128) {
        Bs[512 + tid] = b3[tid];
        Bs[640 + tid] = benc[tid];
    }
    if (tid < 64) Bs[768 + tid] = bdec[tid];
    __syncthreads();  // mbar init + biases visible
    if ((tid & 31) == 0) {
#pragma unroll
        for (int s = 0; s < NSLOT; s++) mbar_arrive(mbE + s * 8);  // prime empty
    }

    const int row0 = blockIdx.x * M_TILE;
    // x -> Af fp16 fragment layout (once); thread handles half2 col pairs.
#pragma unroll
    for (int s = 0; s < (M_TILE * IN_DIM / 2) / NTHREADS; s++) {
        int i = s * NTHREADS + tid;
        int r = i >> 5, cp = i & 31;
        int c = 2 * cp;
        int tile = r >> 4, rowin = r & 15;
        int g = rowin & 7, rh = rowin >> 3;
        int kb = c >> 4, kap = c & 15;
        int reg = 2 * (kap >> 3) + rh;
        int tt = (kap & 7) >> 1;
        const float2 xv = *(const float2*)&x[(size_t)(row0 + r) * IN_DIM + c];
        AfU[tile * AF_TILE_U + kb * 128 + (4 * g + tt) * 4 + reg] =
            h2u(__floats2half2_rn(xv.x, xv.y));
    }
    // first gemm_core's top barrier publishes Af/Bs.

    const int warp = tid >> 5, lane = tid & 31;
    const int mw = warp >> 3, nwp = warp & 7;  // 2 x 8 warp grid
    const int g = lane >> 2, t = lane & 3;
    const int tile0 = mw * 2;
    uint32_t fph = 0, eph = 0;
    int slot = 0;
    const uint4* Af4 = (const uint4*)AfU;
    const uint4* Wb4 = (const uint4*)WbU;

    float C[2][4][4];
    float hreg[2][2][4];  // h state in GEMM3/encoder C-fragment layout

    // ---- encoder: tanh(x @ Wenc + benc) -> hreg, Af kb 0..7 ----
    {
        const int n0 = nwp * 16;  // NF = 2
        gemm_core<IN_DIM, HID>(g_Wenc4, Af4, Wb4, wb_b, C, tile0, nwp, lane,
                               mbF, mbE, fph, eph, slot, t0);
#pragma unroll
        for (int mi = 0; mi < 2; mi++)
#pragma unroll
            for (int j = 0; j < 2; j++) {
                int nb = n0 + 8 * j;
                float v0 = fast_tanh(C[mi][j][0] + Bs[640 + nb + 2 * t]);
                float v1 = fast_tanh(C[mi][j][1] + Bs[640 + nb + 2 * t + 1]);
                float v2 = fast_tanh(C[mi][j][2] + Bs[640 + nb + 2 * t]);
                float v3 = fast_tanh(C[mi][j][3] + Bs[640 + nb + 2 * t + 1]);
                hreg[mi][j][0] = v0; hreg[mi][j][1] = v1;
                hreg[mi][j][2] = v2; hreg[mi][j][3] = v3;
                uint2 st = {h2u(__floats2half2_rn(v0, v1)),
                            h2u(__floats2half2_rn(v2, v3))};
                *(uint2*)&AfU[(tile0 + mi) * AF_TILE_U + (nb >> 4) * 128 +
                              lane * 4 + ((nb & 8) ? 2 : 0)] = st;
            }
    }

#pragma unroll 1
    for (int step = 0; step < NSTEPS; step++) {
#pragma unroll 1
        for (int ev = 0; ev < 4; ev++) {
            // GEMM1: tanh(htmp @ W1 + b1) -> Af kb 0..15
            {
                const int n0 = nwp * 32;  // NF = 4
                gemm_core<HID, HID2>(g_W14, Af4, Wb4, wb_b, C, tile0, nwp, lane,
                                     mbF, mbE, fph, eph, slot, t0);
#pragma unroll
                for (int mi = 0; mi < 2; mi++)
#pragma unroll
                    for (int j = 0; j < 4; j++) {
                        int nb = n0 + 8 * j;
                        float b0 = Bs[nb + 2 * t], b1v = Bs[nb + 2 * t + 1];
                        float v0 = fast_tanh(C[mi][j][0] + b0);
                        float v1 = fast_tanh(C[mi][j][1] + b1v);
                        float v2 = fast_tanh(C[mi][j][2] + b0);
                        float v3 = fast_tanh(C[mi][j][3] + b1v);
                        uint2 st = {h2u(__floats2half2_rn(v0, v1)),
                                    h2u(__floats2half2_rn(v2, v3))};
                        *(uint2*)&AfU[(tile0 + mi) * AF_TILE_U + (nb >> 4) * 128 +
                                      lane * 4 + ((nb & 8) ? 2 : 0)] = st;
                    }
            }
            // GEMM2: tanh(z1 @ W2 + b2) -> Af kb 0..15
            {
                const int n0 = nwp * 32;  // NF = 4
                gemm_core<HID2, HID2>(g_W24, Af4, Wb4, wb_b, C, tile0, nwp,
                                      lane, mbF, mbE, fph, eph, slot, t0);
#pragma unroll
                for (int mi = 0; mi < 2; mi++)
#pragma unroll
                    for (int j = 0; j < 4; j++) {
                        int nb = n0 + 8 * j;
                        float b0 = Bs[256 + nb + 2 * t], b1v = Bs[256 + nb + 2 * t + 1];
                        float v0 = fast_tanh(C[mi][j][0] + b0);
                        float v1 = fast_tanh(C[mi][j][1] + b1v);
                        float v2 = fast_tanh(C[mi][j][2] + b0);
                        float v3 = fast_tanh(C[mi][j][3] + b1v);
                        uint2 st = {h2u(__floats2half2_rn(v0, v1)),
                                    h2u(__floats2half2_rn(v2, v3))};
                        *(uint2*)&AfU[(tile0 + mi) * AF_TILE_U + (nb >> 4) * 128 +
                                      lane * 4 + ((nb & 8) ? 2 : 0)] = st;
                    }
            }
            // GEMM3: k = z2 @ W3 + b3 ; RK4 -> Af kb 0..7, hreg / SMEM Acc
            {
                const int n0 = nwp * 16;  // NF = 2
                gemm_core<HID2, HID>(g_W34, Af4, Wb4, wb_b, C, tile0, nwp, lane,
                                     mbF, mbE, fph, eph, slot, t0);
#pragma unroll
                for (int mi = 0; mi < 2; mi++)
#pragma unroll
                    for (int j = 0; j < 2; j++) {
                        int nb = n0 + 8 * j;
                        float av[4];
#pragma unroll
                        for (int e = 0; e < 4; e++) {
                            int rr = (tile0 + mi) * 16 + g + 8 * (e >> 1);
                            int cc = nb + 2 * t + (e & 1);
                            float kv = C[mi][j][e] + Bs[512 + cc];
                            float h = hreg[mi][j][e];
                            float* ap = &Acc[rr * HS + cc];
                            if (ev == 0) {
                                *ap = kv;
                                av[e] = fmaf(0.5f * DTC, kv, h);
                            } else if (ev == 1) {
                                *ap += 2.0f * kv;
                                av[e] = fmaf(0.5f * DTC, kv, h);
                            } else if (ev == 2) {
                                *ap += 2.0f * kv;
                                av[e] = fmaf(DTC, kv, h);
                            } else {
                                av[e] = fmaf(DTC / 6.0f, *ap + kv, h);
                                hreg[mi][j][e] = av[e];
                            }
                        }
                        uint2 st = {h2u(__floats2half2_rn(av[0], av[1])),
                                    h2u(__floats2half2_rn(av[2], av[3]))};
                        *(uint2*)&AfU[(tile0 + mi) * AF_TILE_U + (nb >> 4) * 128 +
                                      lane * 4 + ((nb & 8) ? 2 : 0)] = st;
                    }
            }
        }
    }

    // ---- decoder: hT @ Wdec + bdec -> out ----
    {
        const int n0 = nwp * 8;  // NF = 1
        gemm_core<HID, OUT_DIM>(g_Wdec4, Af4, Wb4, wb_b, C, tile0, nwp, lane,
                                mbF, mbE, fph, eph, slot, t0);
#pragma unroll
        for (int mi = 0; mi < 2; mi++) {
            int rr0 = (tile0 + mi) * 16 + g;
            float b0 = Bs[768 + n0 + 2 * t], b1v = Bs[768 + n0 + 2 * t + 1];
            float2 o0 = make_float2(C[mi][0][0] + b0, C[mi][0][1] + b1v);
            float2 o1 = make_float2(C[mi][0][2] + b0, C[mi][0][3] + b1v);
            *(float2*)&out[(size_t)(row0 + rr0) * OUT_DIM + n0 + 2 * t] = o0;
            *(float2*)&out[(size_t)(row0 + rr0 + 8) * OUT_DIM + n0 + 2 * t] = o1;
        }
    }
}

static constexpr int SMEM_BYTES =
    (4 * AF_TILE_U + NSLOT * SLOTU) * 4 + M_TILE * HS * 4 + 832 * 4 + 64;
// = 65536 + 33792 + 3328 + 64 = 102,720 B  (2 CTAs/SM: 205 KB < 228 KB)

extern "C" void kernel_launch(void* const* d_in, const int* in_sizes, int n_in,
                              void* d_out, int out_size) {
    const float* x    = (const float*)d_in[0];
    const float* Wenc = (const float*)d_in[1];
    const float* benc = (const float*)d_in[2];
    const float* W1   = (const float*)d_in[3];
    const float* b1   = (const float*)d_in[4];
    const float* W2   = (const float*)d_in[5];
    const float* b2   = (const float*)d_in[6];
    const float* W3   = (const float*)d_in[7];
    const float* b3   = (const float*)d_in[8];
    const float* Wdec = (const float*)d_in[9];
    const float* bdec = (const float*)d_in[10];
    float* out = (float*)d_out;

    const int batch = in_sizes[0] / IN_DIM;  // 65536
    const int grid  = batch / M_TILE;        // 1024

    cudaFuncSetAttribute(node_kernel, cudaFuncAttributeMaxDynamicSharedMemorySize,
                         SMEM_BYTES);

    prep_kernel<<<128, 256>>>(Wenc, W1, W2, W3, Wdec);  // covers 32768 u32 max
    node_kernel<<<grid, NTHREADS, SMEM_BYTES>>>(x, benc, b1, b2, b3, bdec, out);
}

// round 13
// speedup vs baseline: 1.1252x; 1.1252x over previous
#include <cuda_runtime.h>
#include <cuda_fp16.h>
#include <cstdint>

#define IN_DIM   64
#define HID      128
#define HID2     256
#define OUT_DIM  64
#define NSTEPS   20
#define NTHREADS 512
#define NWARP    16
#define M_TILE   64
#define KCH      64            // K rows per staged chunk (4 k16 blocks = 2 pairs)
#define NSLOT    3
#define SLOTU    8192          // u32 per weight slot (max chunk: 32*N = 8192 @ N=256)
#define AF_TILE_U 2048         // u32 per m16 tile in Af (16 kb * 128)

static constexpr float DTC = 1.0f / 20.0f;

// Weights pre-packed (fp16) in b-fragment order:
// [k16pair pk][n8 j][lane(4g+t)][r], r0/r1 = b0/b1 of k16 block 2pk,
// r2/r3 = b0/b1 of block 2pk+1.  b0 = {W[16kb+2t][8j+g], W[16kb+2t+1][..]},
// b1 = same with +8 on k.  uint4 arrays => 16B alignment for cp.async.bulk.
__device__ uint4 g_Wenc4[IN_DIM * HID / 8];
__device__ uint4 g_W14[HID * HID2 / 8];
__device__ uint4 g_W24[HID2 * HID2 / 8];
__device__ uint4 g_W34[HID2 * HID / 8];
__device__ uint4 g_Wdec4[HID * OUT_DIM / 8];

__device__ __forceinline__ uint32_t h2u(__half2 h) {
    return *reinterpret_cast<uint32_t*>(&h);
}

// tanh(x) = 1 - 2/(e^{2x}+1); MUFU ex2/rcp (~1e-6 err), saturates correctly.
__device__ __forceinline__ float fast_tanh(float x) {
    float e;
    asm("ex2.approx.f32 %0, %1;" : "=f"(e) : "f"(x * 2.88539008177792681472f));
    float r;
    asm("rcp.approx.f32 %0, %1;" : "=f"(r) : "f"(e + 1.0f));
    return fmaf(-2.0f, r, 1.0f);
}

__device__ __forceinline__ void mma16(float c[4], const uint4& a, uint32_t b0,
                                      uint32_t b1) {
    asm("mma.sync.aligned.m16n8k16.row.col.f32.f16.f16.f32 "
        "{%0,%1,%2,%3},{%4,%5,%6,%7},{%8,%9},{%0,%1,%2,%3};"
        : "+f"(c[0]), "+f"(c[1]), "+f"(c[2]), "+f"(c[3])
        : "r"(a.x), "r"(a.y), "r"(a.z), "r"(a.w), "r"(b0), "r"(b1));
}

// ---- mbarrier / named-barrier helpers ----
__device__ __forceinline__ void mbar_init(uint32_t mbar, uint32_t cnt) {
    asm volatile("mbarrier.init.shared.b64 [%0], %1;" ::"r"(mbar), "r"(cnt)
                 : "memory");
}
__device__ __forceinline__ void mbar_arrive(uint32_t mbar) {
    asm volatile("mbarrier.arrive.shared.b64 _, [%0];" ::"r"(mbar) : "memory");
}
__device__ __forceinline__ void mbar_wait(uint32_t mbar, uint32_t parity) {
    asm volatile(
        "{\n\t.reg .pred P;\n\t"
        "W_%=:\n\t"
        "mbarrier.try_wait.parity.acquire.cta.shared::cta.b64 P, [%0], %1;\n\t"
        "@!P bra W_%=;\n\t}" ::"r"(mbar),
        "r"(parity)
        : "memory");
}
__device__ __forceinline__ void stage_bulk(uint32_t dst, const void* src,
                                           uint32_t bytes, uint32_t mbar) {
    asm volatile("mbarrier.arrive.expect_tx.shared.b64 _, [%0], %1;" ::"r"(mbar),
                 "r"(bytes)
                 : "memory");
    asm volatile(
        "cp.async.bulk.shared::cta.global.mbarrier::complete_tx::bytes "
        "[%0], [%1], %2, [%3];" ::"r"(dst),
        "l"(src), "r"(bytes), "r"(mbar)
        : "memory");
}
// Group-scoped barrier: 256 threads (8 warps) per barrier id.
__device__ __forceinline__ void barsync(int id) {
    asm volatile("bar.sync %0, %1;" ::"r"(id), "r"(256) : "memory");
}

// C[2][NF][4] += A(group-half: 32 x K, fp16 fragment SMEM) * W(K x N, fp16).
// Per group (8 warps): warp nwp covers 32 rows x N/8 cols; NF = N/64.
// Two groups (mw=0: rows 0-31, mw=1: rows 32-63) run DECOUPLED pipelines,
// sharing only the weight ring. tid0 (group 0) stages chunks via bulk async
// into a 3-slot ring; all warps (both groups) wait per-thread on full(F)
// mbarriers and arrive on empty(E) mbarriers (1/warp; count 16 = both
// groups' uses). Group-local bar.sync brackets each GEMM (Af rows are
// group-disjoint, so no cross-group Af hazards exist).
template <int K, int N>
__device__ __forceinline__ void gemm_core(
    const uint4* __restrict__ Wg, const uint4* __restrict__ Af4,
    const uint4* __restrict__ Wb4, uint32_t wb_b, float C[2][4][4], int tile0,
    int nwp, int lane, uint32_t mbF, uint32_t mbE, uint32_t& fph,
    uint32_t& eph, int& slot, bool t0, int barid) {
    constexpr int NF = N / 64;
    constexpr int N8 = N / 8;
    constexpr int NCH = K / KCH;
    constexpr uint32_t CHU4 = 8 * N;       // uint4 per chunk
    constexpr uint32_t CHB = CHU4 * 16;    // bytes per chunk
#pragma unroll
    for (int mi = 0; mi < 2; mi++)
#pragma unroll
        for (int j = 0; j < NF; j++)
#pragma unroll
            for (int e = 0; e < 4; e++) C[mi][j][e] = 0.0f;

    barsync(barid);  // group's prior epilogue Af writes visible to its warps
    if (t0) {
        const int d = NCH < NSLOT ? NCH : NSLOT;
#pragma unroll
        for (int i = 0; i < d; i++) {
            int s = slot + i;
            if (s >= NSLOT) s -= NSLOT;
            mbar_wait(mbE + s * 8, (eph >> s) & 1u);
            eph ^= 1u << s;
            stage_bulk(wb_b + s * (SLOTU * 4), Wg + i * CHU4, CHB, mbF + s * 8);
        }
    }
    const uint4* Ap0 = Af4 + tile0 * (AF_TILE_U / 4) + lane;
#pragma unroll 1
    for (int ch = 0; ch < NCH; ch++) {
        const int s = slot;
        slot = (slot == NSLOT - 1) ? 0 : slot + 1;
        mbar_wait(mbF + s * 8, (fph >> s) & 1u);
        fph ^= 1u << s;
        const uint4* Ws = Wb4 + s * (SLOTU / 4);
#pragma unroll
        for (int pk = 0; pk < 2; pk++) {
            const int kb0 = ch * 4 + pk * 2;
            uint4 A00 = Ap0[kb0 * 32];
            uint4 A01 = Ap0[(kb0 + 1) * 32];
            uint4 A10 = Ap0[512 + kb0 * 32];
            uint4 A11 = Ap0[512 + (kb0 + 1) * 32];
            uint4 Bv[NF];
#pragma unroll
            for (int j = 0; j < NF; j++)
                Bv[j] = Ws[(pk * N8 + nwp * NF + j) * 32 + lane];
#pragma unroll
            for (int j = 0; j < NF; j++) {
                mma16(C[0][j], A00, Bv[j].x, Bv[j].y);
                mma16(C[1][j], A10, Bv[j].x, Bv[j].y);
            }
#pragma unroll
            for (int j = 0; j < NF; j++) {
                mma16(C[0][j], A01, Bv[j].z, Bv[j].w);
                mma16(C[1][j], A11, Bv[j].z, Bv[j].w);
            }
        }
        __syncwarp();
        if ((threadIdx.x & 31) == 0) mbar_arrive(mbE + s * 8);
        if (t0 && ch + NSLOT < NCH) {
            mbar_wait(mbE + s * 8, (eph >> s) & 1u);
            eph ^= 1u << s;
            stage_bulk(wb_b + s * (SLOTU * 4), Wg + (ch + NSLOT) * CHU4, CHB,
                       mbF + s * 8);
        }
    }
    barsync(barid);  // group's A reads done before its epilogue rewrites Af
}

// Pack W (K x N row-major f32) into fp16 b-fragment order (u32 index i).
__device__ __forceinline__ void packW(int i, int N, const float* src,
                                      uint32_t* dst) {
    int N8 = N / 8;
    int perPk = N8 * 128;
    int pk = i / perPk;
    int rem = i - pk * perPk;
    int j = rem >> 7;
    int l = rem & 127;
    int lane = l >> 2, r = l & 3;
    int g = lane >> 2, t = lane & 3;
    int kb = 2 * pk + (r >> 1);
    int k0 = 16 * kb + 2 * t + 8 * (r & 1);
    int n = 8 * j + g;
    dst[i] = h2u(__floats2half2_rn(src[k0 * N + n], src[(k0 + 1) * N + n]));
}

__global__ void prep_kernel(const float* We, const float* W1, const float* W2,
                            const float* W3, const float* Wd) {
    int i = blockIdx.x * blockDim.x + threadIdx.x;
    if (i < IN_DIM * HID / 2) packW(i, HID, We, (uint32_t*)g_Wenc4);
    if (i < HID * HID2 / 2) packW(i, HID2, W1, (uint32_t*)g_W14);
    if (i < HID2 * HID2 / 2) packW(i, HID2, W2, (uint32_t*)g_W24);
    if (i < HID2 * HID / 2) packW(i, HID, W3, (uint32_t*)g_W34);
    if (i < HID * OUT_DIM / 2) packW(i, OUT_DIM, Wd, (uint32_t*)g_Wdec4);
}

__global__ void __launch_bounds__(NTHREADS, 1)
node_kernel(const float* __restrict__ x, const float* __restrict__ benc,
            const float* __restrict__ b1, const float* __restrict__ b2,
            const float* __restrict__ b3, const float* __restrict__ bdec,
            float* __restrict__ out) {
    extern __shared__ uint32_t smemu[];
    uint32_t* AfU = smemu;                          // [4][16][32][4] u32 (32 KB)
    uint32_t* WbU = AfU + 4 * AF_TILE_U;            // [3][SLOTU] (96 KB)
    float* Bs = (float*)(WbU + NSLOT * SLOTU);      // 832 f32 biases
    uint32_t* Mb = (uint32_t*)(Bs + 832);           // 6 mbarriers (48 B)

    const int tid = threadIdx.x;
    const uint32_t mbF = (uint32_t)__cvta_generic_to_shared(Mb);
    const uint32_t mbE = mbF + NSLOT * 8;
    const uint32_t wb_b = (uint32_t)__cvta_generic_to_shared(WbU);
    const bool t0 = (tid == 0);
    if (t0) {
#pragma unroll
        for (int s = 0; s < NSLOT; s++) {
            mbar_init(mbF + s * 8, 1);
            mbar_init(mbE + s * 8, NWARP);
        }
    }
    if (tid < 256) {
        Bs[tid] = b1[tid];
        Bs[256 + tid] = b2[tid];
    }
    if (tid < 128) {
        Bs[512 + tid] = b3[tid];
        Bs[640 + tid] = benc[tid];
    }
    if (tid < 64) Bs[768 + tid] = bdec[tid];
    __syncthreads();  // one-time: mbar init + biases visible to ALL warps
    if ((tid & 31) == 0) {
#pragma unroll
        for (int s = 0; s < NSLOT; s++) mbar_arrive(mbE + s * 8);  // prime empty
    }

    const int row0 = blockIdx.x * M_TILE;
    // x -> Af fp16 fragment layout (once); thread handles half2 col pairs.
#pragma unroll
    for (int s = 0; s < (M_TILE * IN_DIM / 2) / NTHREADS; s++) {
        int i = s * NTHREADS + tid;
        int r = i >> 5, cp = i & 31;
        int c = 2 * cp;
        int tile = r >> 4, rowin = r & 15;
        int g = rowin & 7, rh = rowin >> 3;
        int kb = c >> 4, kap = c & 15;
        int reg = 2 * (kap >> 3) + rh;
        int tt = (kap & 7) >> 1;
        const float2 xv = *(const float2*)&x[(size_t)(row0 + r) * IN_DIM + c];
        AfU[tile * AF_TILE_U + kb * 128 + (4 * g + tt) * 4 + reg] =
            h2u(__floats2half2_rn(xv.x, xv.y));
    }
    __syncthreads();  // one-time: x staging visible to ALL warps (cross-group)

    const int warp = tid >> 5, lane = tid & 31;
    const int mw = warp >> 3, nwp = warp & 7;  // group (M-half) x 8 N-warps
    const int g = lane >> 2, t = lane & 3;
    const int tile0 = mw * 2;
    const int barid = 1 + mw;  // group-scoped named barrier
    uint32_t fph = 0, eph = 0;
    int slot = 0;
    const uint4* Af4 = (const uint4*)AfU;
    const uint4* Wb4 = (const uint4*)WbU;

    float C[2][4][4];
    float hreg[2][2][4];  // h state in GEMM3/encoder C-fragment layout
    float acc[2][2][4];   // RK4 accumulator, same layout

    // ---- encoder: tanh(x @ Wenc + benc) -> hreg, Af kb 0..7 ----
    {
        const int n0 = nwp * 16;  // NF = 2
        gemm_core<IN_DIM, HID>(g_Wenc4, Af4, Wb4, wb_b, C, tile0, nwp, lane,
                               mbF, mbE, fph, eph, slot, t0, barid);
#pragma unroll
        for (int mi = 0; mi < 2; mi++)
#pragma unroll
            for (int j = 0; j < 2; j++) {
                int nb = n0 + 8 * j;
                float v0 = fast_tanh(C[mi][j][0] + Bs[640 + nb + 2 * t]);
                float v1 = fast_tanh(C[mi][j][1] + Bs[640 + nb + 2 * t + 1]);
                float v2 = fast_tanh(C[mi][j][2] + Bs[640 + nb + 2 * t]);
                float v3 = fast_tanh(C[mi][j][3] + Bs[640 + nb + 2 * t + 1]);
                hreg[mi][j][0] = v0; hreg[mi][j][1] = v1;
                hreg[mi][j][2] = v2; hreg[mi][j][3] = v3;
                uint2 st = {h2u(__floats2half2_rn(v0, v1)),
                            h2u(__floats2half2_rn(v2, v3))};
                *(uint2*)&AfU[(tile0 + mi) * AF_TILE_U + (nb >> 4) * 128 +
                              lane * 4 + ((nb & 8) ? 2 : 0)] = st;
            }
    }

#pragma unroll 1
    for (int step = 0; step < NSTEPS; step++) {
#pragma unroll 1
        for (int ev = 0; ev < 4; ev++) {
            // GEMM1: tanh(htmp @ W1 + b1) -> Af kb 0..15
            {
                const int n0 = nwp * 32;  // NF = 4
                gemm_core<HID, HID2>(g_W14, Af4, Wb4, wb_b, C, tile0, nwp, lane,
                                     mbF, mbE, fph, eph, slot, t0, barid);
#pragma unroll
                for (int mi = 0; mi < 2; mi++)
#pragma unroll
                    for (int j = 0; j < 4; j++) {
                        int nb = n0 + 8 * j;
                        float b0 = Bs[nb + 2 * t], b1v = Bs[nb + 2 * t + 1];
                        float v0 = fast_tanh(C[mi][j][0] + b0);
                        float v1 = fast_tanh(C[mi][j][1] + b1v);
                        float v2 = fast_tanh(C[mi][j][2] + b0);
                        float v3 = fast_tanh(C[mi][j][3] + b1v);
                        uint2 st = {h2u(__floats2half2_rn(v0, v1)),
                                    h2u(__floats2half2_rn(v2, v3))};
                        *(uint2*)&AfU[(tile0 + mi) * AF_TILE_U + (nb >> 4) * 128 +
                                      lane * 4 + ((nb & 8) ? 2 : 0)] = st;
                    }
            }
            // GEMM2: tanh(z1 @ W2 + b2) -> Af kb 0..15
            {
                const int n0 = nwp * 32;  // NF = 4
                gemm_core<HID2, HID2>(g_W24, Af4, Wb4, wb_b, C, tile0, nwp,
                                      lane, mbF, mbE, fph, eph, slot, t0, barid);
#pragma unroll
                for (int mi = 0; mi < 2; mi++)
#pragma unroll
                    for (int j = 0; j < 4; j++) {
                        int nb = n0 + 8 * j;
                        float b0 = Bs[256 + nb + 2 * t], b1v = Bs[256 + nb + 2 * t + 1];
                        float v0 = fast_tanh(C[mi][j][0] + b0);
                        float v1 = fast_tanh(C[mi][j][1] + b1v);
                        float v2 = fast_tanh(C[mi][j][2] + b0);
                        float v3 = fast_tanh(C[mi][j][3] + b1v);
                        uint2 st = {h2u(__floats2half2_rn(v0, v1)),
                                    h2u(__floats2half2_rn(v2, v3))};
                        *(uint2*)&AfU[(tile0 + mi) * AF_TILE_U + (nb >> 4) * 128 +
                                      lane * 4 + ((nb & 8) ? 2 : 0)] = st;
                    }
            }
            // GEMM3: k = z2 @ W3 + b3 ; RK4 -> Af kb 0..7, hreg/acc
            {
                const int n0 = nwp * 16;  // NF = 2
                gemm_core<HID2, HID>(g_W34, Af4, Wb4, wb_b, C, tile0, nwp, lane,
                                     mbF, mbE, fph, eph, slot, t0, barid);
#pragma unroll
                for (int mi = 0; mi < 2; mi++)
#pragma unroll
                    for (int j = 0; j < 2; j++) {
                        int nb = n0 + 8 * j;
                        float av[4];
#pragma unroll
                        for (int e = 0; e < 4; e++) {
                            float kv = C[mi][j][e] + Bs[512 + nb + 2 * t + (e & 1)];
                            float h = hreg[mi][j][e];
                            if (ev == 0) {
                                acc[mi][j][e] = kv;
                                av[e] = fmaf(0.5f * DTC, kv, h);
                            } else if (ev == 1) {
                                acc[mi][j][e] += 2.0f * kv;
                                av[e] = fmaf(0.5f * DTC, kv, h);
                            } else if (ev == 2) {
                                acc[mi][j][e] += 2.0f * kv;
                                av[e] = fmaf(DTC, kv, h);
                            } else {
                                av[e] = fmaf(DTC / 6.0f, acc[mi][j][e] + kv, h);
                                hreg[mi][j][e] = av[e];
                            }
                        }
                        uint2 st = {h2u(__floats2half2_rn(av[0], av[1])),
                                    h2u(__floats2half2_rn(av[2], av[3]))};
                        *(uint2*)&AfU[(tile0 + mi) * AF_TILE_U + (nb >> 4) * 128 +
                                      lane * 4 + ((nb & 8) ? 2 : 0)] = st;
                    }
            }
        }
    }

    // ---- decoder: hT @ Wdec + bdec -> out ----
    {
        const int n0 = nwp * 8;  // NF = 1
        gemm_core<HID, OUT_DIM>(g_Wdec4, Af4, Wb4, wb_b, C, tile0, nwp, lane,
                                mbF, mbE, fph, eph, slot, t0, barid);
#pragma unroll
        for (int mi = 0; mi < 2; mi++) {
            int rr0 = (tile0 + mi) * 16 + g;
            float b0 = Bs[768 + n0 + 2 * t], b1v = Bs[768 + n0 + 2 * t + 1];
            float2 o0 = make_float2(C[mi][0][0] + b0, C[mi][0][1] + b1v);
            float2 o1 = make_float2(C[mi][0][2] + b0, C[mi][0][3] + b1v);
            *(float2*)&out[(size_t)(row0 + rr0) * OUT_DIM + n0 + 2 * t] = o0;
            *(float2*)&out[(size_t)(row0 + rr0 + 8) * OUT_DIM + n0 + 2 * t] = o1;
        }
    }
}

static constexpr int SMEM_BYTES =
    (4 * AF_TILE_U + NSLOT * SLOTU) * 4 + 832 * 4 + 64;  // 134,528 B

extern "C" void kernel_launch(void* const* d_in, const int* in_sizes, int n_in,
                              void* d_out, int out_size) {
    const float* x    = (const float*)d_in[0];
    const float* Wenc = (const float*)d_in[1];
    const float* benc = (const float*)d_in[2];
    const float* W1   = (const float*)d_in[3];
    const float* b1   = (const float*)d_in[4];
    const float* W2   = (const float*)d_in[5];
    const float* b2   = (const float*)d_in[6];
    const float* W3   = (const float*)d_in[7];
    const float* b3   = (const float*)d_in[8];
    const float* Wdec = (const float*)d_in[9];
    const float* bdec = (const float*)d_in[10];
    float* out = (float*)d_out;

    const int batch = in_sizes[0] / IN_DIM;  // 65536
    const int grid  = batch / M_TILE;        // 1024

    cudaFuncSetAttribute(node_kernel, cudaFuncAttributeMaxDynamicSharedMemorySize,
                         SMEM_BYTES);

    prep_kernel<<<128, 256>>>(Wenc, W1, W2, W3, Wdec);  // covers 32768 u32 max
    node_kernel<<<grid, NTHREADS, SMEM_BYTES>>>(x, benc, b1, b2, b3, bdec, out);
}

// round 14
// speedup vs baseline: 1.2785x; 1.1363x over previous
#include <cuda_runtime.h>
#include <cuda_fp16.h>
#include <cstdint>

#define IN_DIM   64
#define HID      128
#define HID2     256
#define OUT_DIM  64
#define NSTEPS   20
#define NTHREADS 512
#define NWARP    16
#define M_TILE   64
#define KCH      64            // K rows per staged chunk (4 k16 blocks = 2 pairs)
#define NSLOT    3
#define SLOTU    8192          // u32 per weight slot (max chunk: 32*N = 8192 @ N=256)
#define AF_TILE_U 2048         // u32 per m16 tile in Af (16 kb * 128)

static constexpr float DTC = 1.0f / 20.0f;

// Weights pre-packed (fp16) in b-fragment order:
// [k16pair pk][n8 j][lane(4g+t)][r], r0/r1 = b0/b1 of k16 block 2pk,
// r2/r3 = b0/b1 of block 2pk+1.  b0 = {W[16kb+2t][8j+g], W[16kb+2t+1][..]},
// b1 = same with +8 on k.  uint4 arrays => 16B alignment for cp.async.bulk.
__device__ uint4 g_Wenc4[IN_DIM * HID / 8];
__device__ uint4 g_W14[HID * HID2 / 8];
__device__ uint4 g_W24[HID2 * HID2 / 8];
__device__ uint4 g_W34[HID2 * HID / 8];
__device__ uint4 g_Wdec4[HID * OUT_DIM / 8];

__device__ __forceinline__ uint32_t h2u(__half2 h) {
    return *reinterpret_cast<uint32_t*>(&h);
}

// Single-instruction MUFU.TANH (sm_75+): 1 MUFU vs 2 MUFU + FMA chain.
__device__ __forceinline__ float fast_tanh(float x) {
    float r;
    asm("tanh.approx.f32 %0, %1;" : "=f"(r) : "f"(x));
    return r;
}

__device__ __forceinline__ void mma16(float c[4], const uint4& a, uint32_t b0,
                                      uint32_t b1) {
    asm("mma.sync.aligned.m16n8k16.row.col.f32.f16.f16.f32 "
        "{%0,%1,%2,%3},{%4,%5,%6,%7},{%8,%9},{%0,%1,%2,%3};"
        : "+f"(c[0]), "+f"(c[1]), "+f"(c[2]), "+f"(c[3])
        : "r"(a.x), "r"(a.y), "r"(a.z), "r"(a.w), "r"(b0), "r"(b1));
}

// ---- mbarrier / named-barrier helpers ----
__device__ __forceinline__ void mbar_init(uint32_t mbar, uint32_t cnt) {
    asm volatile("mbarrier.init.shared.b64 [%0], %1;" ::"r"(mbar), "r"(cnt)
                 : "memory");
}
__device__ __forceinline__ void mbar_arrive(uint32_t mbar) {
    asm volatile("mbarrier.arrive.shared.b64 _, [%0];" ::"r"(mbar) : "memory");
}
__device__ __forceinline__ void mbar_wait(uint32_t mbar, uint32_t parity) {
    asm volatile(
        "{\n\t.reg .pred P;\n\t"
        "W_%=:\n\t"
        "mbarrier.try_wait.parity.acquire.cta.shared::cta.b64 P, [%0], %1;\n\t"
        "@!P bra W_%=;\n\t}" ::"r"(mbar),
        "r"(parity)
        : "memory");
}
__device__ __forceinline__ void stage_bulk(uint32_t dst, const void* src,
                                           uint32_t bytes, uint32_t mbar) {
    asm volatile("mbarrier.arrive.expect_tx.shared.b64 _, [%0], %1;" ::"r"(mbar),
                 "r"(bytes)
                 : "memory");
    asm volatile(
        "cp.async.bulk.shared::cta.global.mbarrier::complete_tx::bytes "
        "[%0], [%1], %2, [%3];" ::"r"(dst),
        "l"(src), "r"(bytes), "r"(mbar)
        : "memory");
}
// Group-scoped barrier: 256 threads (8 warps) per barrier id.
__device__ __forceinline__ void barsync(int id) {
    asm volatile("bar.sync %0, %1;" ::"r"(id), "r"(256) : "memory");
}

// C[2][NF][4] += A(group-half: 32 x K, fp16 fragment SMEM) * W(K x N, fp16).
// Per group (8 warps): warp nwp covers 32 rows x N/8 cols; NF = N/64.
// Two groups (mw=0: rows 0-31, mw=1: rows 32-63) run decoupled pipelines,
// sharing only the weight ring (empties need all 16 warps). Group-local
// bar.sync brackets each GEMM (Af rows are group-disjoint).
template <int K, int N>
__device__ __forceinline__ void gemm_core(
    const uint4* __restrict__ Wg, const uint4* __restrict__ Af4,
    const uint4* __restrict__ Wb4, uint32_t wb_b, float C[2][4][4], int tile0,
    int nwp, int lane, uint32_t mbF, uint32_t mbE, uint32_t& fph,
    uint32_t& eph, int& slot, bool t0, int barid) {
    constexpr int NF = N / 64;
    constexpr int N8 = N / 8;
    constexpr int NCH = K / KCH;
    constexpr uint32_t CHU4 = 8 * N;       // uint4 per chunk
    constexpr uint32_t CHB = CHU4 * 16;    // bytes per chunk
#pragma unroll
    for (int mi = 0; mi < 2; mi++)
#pragma unroll
        for (int j = 0; j < NF; j++)
#pragma unroll
            for (int e = 0; e < 4; e++) C[mi][j][e] = 0.0f;

    barsync(barid);  // group's prior epilogue Af writes visible to its warps
    if (t0) {
        const int d = NCH < NSLOT ? NCH : NSLOT;
#pragma unroll
        for (int i = 0; i < d; i++) {
            int s = slot + i;
            if (s >= NSLOT) s -= NSLOT;
            mbar_wait(mbE + s * 8, (eph >> s) & 1u);
            eph ^= 1u << s;
            stage_bulk(wb_b + s * (SLOTU * 4), Wg + i * CHU4, CHB, mbF + s * 8);
        }
    }
    const uint4* Ap0 = Af4 + tile0 * (AF_TILE_U / 4) + lane;
#pragma unroll 1
    for (int ch = 0; ch < NCH; ch++) {
        const int s = slot;
        slot = (slot == NSLOT - 1) ? 0 : slot + 1;
        mbar_wait(mbF + s * 8, (fph >> s) & 1u);
        fph ^= 1u << s;
        const uint4* Ws = Wb4 + s * (SLOTU / 4);
#pragma unroll
        for (int pk = 0; pk < 2; pk++) {
            const int kb0 = ch * 4 + pk * 2;
            uint4 A00 = Ap0[kb0 * 32];
            uint4 A01 = Ap0[(kb0 + 1) * 32];
            uint4 A10 = Ap0[512 + kb0 * 32];
            uint4 A11 = Ap0[512 + (kb0 + 1) * 32];
            uint4 Bv[NF];
#pragma unroll
            for (int j = 0; j < NF; j++)
                Bv[j] = Ws[(pk * N8 + nwp * NF + j) * 32 + lane];
#pragma unroll
            for (int j = 0; j < NF; j++) {
                mma16(C[0][j], A00, Bv[j].x, Bv[j].y);
                mma16(C[1][j], A10, Bv[j].x, Bv[j].y);
            }
#pragma unroll
            for (int j = 0; j < NF; j++) {
                mma16(C[0][j], A01, Bv[j].z, Bv[j].w);
                mma16(C[1][j], A11, Bv[j].z, Bv[j].w);
            }
        }
        __syncwarp();
        if ((threadIdx.x & 31) == 0) mbar_arrive(mbE + s * 8);
        if (t0 && ch + NSLOT < NCH) {
            mbar_wait(mbE + s * 8, (eph >> s) & 1u);
            eph ^= 1u << s;
            stage_bulk(wb_b + s * (SLOTU * 4), Wg + (ch + NSLOT) * CHU4, CHB,
                       mbF + s * 8);
        }
    }
    barsync(barid);  // group's A reads done before its epilogue rewrites Af
}

// Pack W (K x N row-major f32) into fp16 b-fragment order (u32 index i).
__device__ __forceinline__ void packW(int i, int N, const float* src,
                                      uint32_t* dst) {
    int N8 = N / 8;
    int perPk = N8 * 128;
    int pk = i / perPk;
    int rem = i - pk * perPk;
    int j = rem >> 7;
    int l = rem & 127;
    int lane = l >> 2, r = l & 3;
    int g = lane >> 2, t = lane & 3;
    int kb = 2 * pk + (r >> 1);
    int k0 = 16 * kb + 2 * t + 8 * (r & 1);
    int n = 8 * j + g;
    dst[i] = h2u(__floats2half2_rn(src[k0 * N + n], src[(k0 + 1) * N + n]));
}

__global__ void prep_kernel(const float* We, const float* W1, const float* W2,
                            const float* W3, const float* Wd) {
    int i = blockIdx.x * blockDim.x + threadIdx.x;
    if (i < IN_DIM * HID / 2) packW(i, HID, We, (uint32_t*)g_Wenc4);
    if (i < HID * HID2 / 2) packW(i, HID2, W1, (uint32_t*)g_W14);
    if (i < HID2 * HID2 / 2) packW(i, HID2, W2, (uint32_t*)g_W24);
    if (i < HID2 * HID / 2) packW(i, HID, W3, (uint32_t*)g_W34);
    if (i < HID * OUT_DIM / 2) packW(i, OUT_DIM, Wd, (uint32_t*)g_Wdec4);
}

__global__ void __launch_bounds__(NTHREADS, 1)
node_kernel(const float* __restrict__ x, const float* __restrict__ benc,
            const float* __restrict__ b1, const float* __restrict__ b2,
            const float* __restrict__ b3, const float* __restrict__ bdec,
            float* __restrict__ out) {
    extern __shared__ uint32_t smemu[];
    uint32_t* AfU = smemu;                          // [4][16][32][4] u32 (32 KB)
    uint32_t* WbU = AfU + 4 * AF_TILE_U;            // [3][SLOTU] (96 KB)
    float* Bs = (float*)(WbU + NSLOT * SLOTU);      // 832 f32 biases
    uint32_t* Mb = (uint32_t*)(Bs + 832);           // 6 mbarriers (48 B)

    const int tid = threadIdx.x;
    const uint32_t mbF = (uint32_t)__cvta_generic_to_shared(Mb);
    const uint32_t mbE = mbF + NSLOT * 8;
    const uint32_t wb_b = (uint32_t)__cvta_generic_to_shared(WbU);
    const bool t0 = (tid == 0);
    if (t0) {
#pragma unroll
        for (int s = 0; s < NSLOT; s++) {
            mbar_init(mbF + s * 8, 1);
            mbar_init(mbE + s * 8, NWARP);
        }
    }
    if (tid < 256) {
        Bs[tid] = b1[tid];
        Bs[256 + tid] = b2[tid];
    }
    if (tid < 128) {
        Bs[512 + tid] = b3[tid];
        Bs[640 + tid] = benc[tid];
    }
    if (tid < 64) Bs[768 + tid] = bdec[tid];
    __syncthreads();  // one-time: mbar init + biases visible to ALL warps
    if ((tid & 31) == 0) {
#pragma unroll
        for (int s = 0; s < NSLOT; s++) mbar_arrive(mbE + s * 8);  // prime empty
    }

    const int row0 = blockIdx.x * M_TILE;
    // x -> Af fp16 fragment layout (once); thread handles half2 col pairs.
#pragma unroll
    for (int s = 0; s < (M_TILE * IN_DIM / 2) / NTHREADS; s++) {
        int i = s * NTHREADS + tid;
        int r = i >> 5, cp = i & 31;
        int c = 2 * cp;
        int tile = r >> 4, rowin = r & 15;
        int g = rowin & 7, rh = rowin >> 3;
        int kb = c >> 4, kap = c & 15;
        int reg = 2 * (kap >> 3) + rh;
        int tt = (kap & 7) >> 1;
        const float2 xv = *(const float2*)&x[(size_t)(row0 + r) * IN_DIM + c];
        AfU[tile * AF_TILE_U + kb * 128 + (4 * g + tt) * 4 + reg] =
            h2u(__floats2half2_rn(xv.x, xv.y));
    }
    __syncthreads();  // one-time: x staging visible to ALL warps (cross-group)

    const int warp = tid >> 5, lane = tid & 31;
    const int mw = warp >> 3, nwp = warp & 7;  // group (M-half) x 8 N-warps
    const int g = lane >> 2, t = lane & 3;
    const int tile0 = mw * 2;
    const int barid = 1 + mw;  // group-scoped named barrier
    uint32_t fph = 0, eph = 0;
    int slot = 0;
    const uint4* Af4 = (const uint4*)AfU;
    const uint4* Wb4 = (const uint4*)WbU;

    float C[2][4][4];
    float hreg[2][2][4];  // h state in GEMM3/encoder C-fragment layout
    float acc[2][2][4];   // RK4 accumulator, same layout

    // ---- encoder: tanh(x @ Wenc + benc) -> hreg, Af kb 0..7 ----
    {
        const int n0 = nwp * 16;  // NF = 2
        gemm_core<IN_DIM, HID>(g_Wenc4, Af4, Wb4, wb_b, C, tile0, nwp, lane,
                               mbF, mbE, fph, eph, slot, t0, barid);
#pragma unroll
        for (int mi = 0; mi < 2; mi++)
#pragma unroll
            for (int j = 0; j < 2; j++) {
                int nb = n0 + 8 * j;
                float v0 = fast_tanh(C[mi][j][0] + Bs[640 + nb + 2 * t]);
                float v1 = fast_tanh(C[mi][j][1] + Bs[640 + nb + 2 * t + 1]);
                float v2 = fast_tanh(C[mi][j][2] + Bs[640 + nb + 2 * t]);
                float v3 = fast_tanh(C[mi][j][3] + Bs[640 + nb + 2 * t + 1]);
                hreg[mi][j][0] = v0; hreg[mi][j][1] = v1;
                hreg[mi][j][2] = v2; hreg[mi][j][3] = v3;
                uint2 st = {h2u(__floats2half2_rn(v0, v1)),
                            h2u(__floats2half2_rn(v2, v3))};
                *(uint2*)&AfU[(tile0 + mi) * AF_TILE_U + (nb >> 4) * 128 +
                              lane * 4 + ((nb & 8) ? 2 : 0)] = st;
            }
    }

#pragma unroll 1
    for (int step = 0; step < NSTEPS; step++) {
#pragma unroll 1
        for (int ev = 0; ev < 4; ev++) {
            // GEMM1: tanh(htmp @ W1 + b1) -> Af kb 0..15
            {
                const int n0 = nwp * 32;  // NF = 4
                gemm_core<HID, HID2>(g_W14, Af4, Wb4, wb_b, C, tile0, nwp, lane,
                                     mbF, mbE, fph, eph, slot, t0, barid);
#pragma unroll
                for (int mi = 0; mi < 2; mi++)
#pragma unroll
                    for (int j = 0; j < 4; j++) {
                        int nb = n0 + 8 * j;
                        float b0 = Bs[nb + 2 * t], b1v = Bs[nb + 2 * t + 1];
                        float v0 = fast_tanh(C[mi][j][0] + b0);
                        float v1 = fast_tanh(C[mi][j][1] + b1v);
                        float v2 = fast_tanh(C[mi][j][2] + b0);
                        float v3 = fast_tanh(C[mi][j][3] + b1v);
                        uint2 st = {h2u(__floats2half2_rn(v0, v1)),
                                    h2u(__floats2half2_rn(v2, v3))};
                        *(uint2*)&AfU[(tile0 + mi) * AF_TILE_U + (nb >> 4) * 128 +
                                      lane * 4 + ((nb & 8) ? 2 : 0)] = st;
                    }
            }
            // GEMM2: tanh(z1 @ W2 + b2) -> Af kb 0..15
            {
                const int n0 = nwp * 32;  // NF = 4
                gemm_core<HID2, HID2>(g_W24, Af4, Wb4, wb_b, C, tile0, nwp,
                                      lane, mbF, mbE, fph, eph, slot, t0, barid);
#pragma unroll
                for (int mi = 0; mi < 2; mi++)
#pragma unroll
                    for (int j = 0; j < 4; j++) {
                        int nb = n0 + 8 * j;
                        float b0 = Bs[256 + nb + 2 * t], b1v = Bs[256 + nb + 2 * t + 1];
                        float v0 = fast_tanh(C[mi][j][0] + b0);
                        float v1 = fast_tanh(C[mi][j][1] + b1v);
                        float v2 = fast_tanh(C[mi][j][2] + b0);
                        float v3 = fast_tanh(C[mi][j][3] + b1v);
                        uint2 st = {h2u(__floats2half2_rn(v0, v1)),
                                    h2u(__floats2half2_rn(v2, v3))};
                        *(uint2*)&AfU[(tile0 + mi) * AF_TILE_U + (nb >> 4) * 128 +
                                      lane * 4 + ((nb & 8) ? 2 : 0)] = st;
                    }
            }
            // GEMM3: k = z2 @ W3 + b3 ; RK4 -> Af kb 0..7, hreg/acc
            {
                const int n0 = nwp * 16;  // NF = 2
                gemm_core<HID2, HID>(g_W34, Af4, Wb4, wb_b, C, tile0, nwp, lane,
                                     mbF, mbE, fph, eph, slot, t0, barid);
#pragma unroll
                for (int mi = 0; mi < 2; mi++)
#pragma unroll
                    for (int j = 0; j < 2; j++) {
                        int nb = n0 + 8 * j;
                        float av[4];
#pragma unroll
                        for (int e = 0; e < 4; e++) {
                            float kv = C[mi][j][e] + Bs[512 + nb + 2 * t + (e & 1)];
                            float h = hreg[mi][j][e];
                            if (ev == 0) {
                                acc[mi][j][e] = kv;
                                av[e] = fmaf(0.5f * DTC, kv, h);
                            } else if (ev == 1) {
                                acc[mi][j][e] += 2.0f * kv;
                                av[e] = fmaf(0.5f * DTC, kv, h);
                            } else if (ev == 2) {
                                acc[mi][j][e] += 2.0f * kv;
                                av[e] = fmaf(DTC, kv, h);
                            } else {
                                av[e] = fmaf(DTC / 6.0f, acc[mi][j][e] + kv, h);
                                hreg[mi][j][e] = av[e];
                            }
                        }
                        uint2 st = {h2u(__floats2half2_rn(av[0], av[1])),
                                    h2u(__floats2half2_rn(av[2], av[3]))};
                        *(uint2*)&AfU[(tile0 + mi) * AF_TILE_U + (nb >> 4) * 128 +
                                      lane * 4 + ((nb & 8) ? 2 : 0)] = st;
                    }
            }
        }
    }

    // ---- decoder: hT @ Wdec + bdec -> out ----
    {
        const int n0 = nwp * 8;  // NF = 1
        gemm_core<HID, OUT_DIM>(g_Wdec4, Af4, Wb4, wb_b, C, tile0, nwp, lane,
                                mbF, mbE, fph, eph, slot, t0, barid);
#pragma unroll
        for (int mi = 0; mi < 2; mi++) {
            int rr0 = (tile0 + mi) * 16 + g;
            float b0 = Bs[768 + n0 + 2 * t], b1v = Bs[768 + n0 + 2 * t + 1];
            float2 o0 = make_float2(C[mi][0][0] + b0, C[mi][0][1] + b1v);
            float2 o1 = make_float2(C[mi][0][2] + b0, C[mi][0][3] + b1v);
            *(float2*)&out[(size_t)(row0 + rr0) * OUT_DIM + n0 + 2 * t] = o0;
            *(float2*)&out[(size_t)(row0 + rr0 + 8) * OUT_DIM + n0 + 2 * t] = o1;
        }
    }
}

static constexpr int SMEM_BYTES =
    (4 * AF_TILE_U + NSLOT * SLOTU) * 4 + 832 * 4 + 64;  // 134,528 B

extern "C" void kernel_launch(void* const* d_in, const int* in_sizes, int n_in,
                              void* d_out, int out_size) {
    const float* x    = (const float*)d_in[0];
    const float* Wenc = (const float*)d_in[1];
    const float* benc = (const float*)d_in[2];
    const float* W1   = (const float*)d_in[3];
    const float* b1   = (const float*)d_in[4];
    const float* W2   = (const float*)d_in[5];
    const float* b2   = (const float*)d_in[6];
    const float* W3   = (const float*)d_in[7];
    const float* b3   = (const float*)d_in[8];
    const float* Wdec = (const float*)d_in[9];
    const float* bdec = (const float*)d_in[10];
    float* out = (float*)d_out;

    const int batch = in_sizes[0] / IN_DIM;  // 65536
    const int grid  = batch / M_TILE;        // 1024

    cudaFuncSetAttribute(node_kernel, cudaFuncAttributeMaxDynamicSharedMemorySize,
                         SMEM_BYTES);

    prep_kernel<<<128, 256>>>(Wenc, W1, W2, W3, Wdec);  // covers 32768 u32 max
    node_kernel<<<grid, NTHREADS, SMEM_BYTES>>>(x, benc, b1, b2, b3, bdec, out);
}